// round 1
// baseline (speedup 1.0000x reference)
#include <cuda_runtime.h>
#include <cuda_bf16.h>
#include <cstdint>

// Problem constants (fixed by the dataset; guarded at launch time)
#define NMAX 100000
#define GMAX 128
#define HID  64

// ---------------- scratch (no allocations allowed) ----------------
__device__ float g_dinv[NMAX];            // deg -> rsqrt(deg)
__device__ float g_bufA[(size_t)NMAX * HID];
__device__ float g_bufB[(size_t)NMAX * HID];
__device__ float g_pool[GMAX * HID];
__device__ float g_cnt[GMAX];

// ---------------- degree / dinv ----------------
__global__ void k_deg_init(int n) {
    int i = blockIdx.x * blockDim.x + threadIdx.x;
    if (i < n) g_dinv[i] = 1.0f;          // self loop contributes 1
}

__global__ void k_deg_count(const int* __restrict__ dst, int E) {
    int i = blockIdx.x * blockDim.x + threadIdx.x;
    if (i < E) atomicAdd(&g_dinv[dst[i]], 1.0f);
}

__global__ void k_dinv_finish(int n) {
    int i = blockIdx.x * blockDim.x + threadIdx.x;
    if (i < n) g_dinv[i] = rsqrtf(g_dinv[i]);
}

// ---------------- dense GEMM: Y[n,64] = X[n,K] @ W[K,64] ----------------
// one warp per node row; W staged in smem; x row in registers, shfl-broadcast
template <int K>
__global__ void k_gemm_nodes(const float* __restrict__ X,
                             const float* __restrict__ Wg,
                             float* __restrict__ Y, int n) {
    constexpr int Q = K / 32;
    __shared__ float Ws[K * HID];
    for (int i = threadIdx.x; i < K * HID; i += blockDim.x) Ws[i] = Wg[i];
    __syncthreads();

    int gw   = (blockIdx.x * blockDim.x + threadIdx.x) >> 5;
    int lane = threadIdx.x & 31;
    if (gw >= n) return;

    float xv[Q];
    const float* xr = X + (size_t)gw * K + lane * Q;
#pragma unroll
    for (int q = 0; q < Q; q++) xv[q] = xr[q];

    float a0 = 0.f, a1 = 0.f;
#pragma unroll
    for (int kk = 0; kk < 32; kk++) {
#pragma unroll
        for (int q = 0; q < Q; q++) {
            float xk = __shfl_sync(0xffffffffu, xv[q], kk);
            int k = kk * Q + q;
            a0 = fmaf(xk, Ws[k * HID + lane], a0);
            a1 = fmaf(xk, Ws[k * HID + 32 + lane], a1);
        }
    }
    Y[(size_t)gw * HID + lane]      = a0;
    Y[(size_t)gw * HID + 32 + lane] = a1;
}

// ---------------- self-loop init: acc = xw * dinv^2 ----------------
__global__ void k_self_init(const float* __restrict__ xw,
                            float* __restrict__ acc, int n) {
    int t = blockIdx.x * blockDim.x + threadIdx.x;   // one float4 per thread
    if (t >= n * 16) return;
    int node = t >> 4;
    float di = g_dinv[node];
    float s  = di * di;
    float4 v = *(const float4*)(xw + (size_t)t * 4);
    v.x *= s; v.y *= s; v.z *= s; v.w *= s;
    *(float4*)(acc + (size_t)t * 4) = v;
}

// ---------------- edge scatter: acc[dst] += xw[src] * dinv[s]*dinv[d] ----
__global__ void k_scatter(const int* __restrict__ src,
                          const int* __restrict__ dst,
                          const float* __restrict__ xw,
                          float* __restrict__ acc, int E) {
    int t = blockIdx.x * blockDim.x + threadIdx.x;
    int e  = t >> 4;          // 16 threads (float4 lanes) per edge
    int jg = t & 15;
    if (e >= E) return;
    int s = __ldg(src + e);
    int d = __ldg(dst + e);
    float norm = g_dinv[s] * g_dinv[d];
    float4 v = *(const float4*)(xw + (size_t)s * HID + jg * 4);
    v.x *= norm; v.y *= norm; v.z *= norm; v.w *= norm;
    atomicAdd((float4*)(acc + (size_t)d * HID + jg * 4), v);   // sm_90+ vector red
}

// ---------------- epilogue layer1: h = relu(acc + b1) ----------------
__global__ void k_bias_relu(const float* __restrict__ acc,
                            const float* __restrict__ b,
                            float* __restrict__ h, int n) {
    int t = blockIdx.x * blockDim.x + threadIdx.x;   // one float4 per thread
    if (t >= n * 16) return;
    int jg = t & 15;
    float4 v  = *(const float4*)(acc + (size_t)t * 4);
    float4 bv = *(const float4*)(b + jg * 4);
    v.x = fmaxf(v.x + bv.x, 0.f);
    v.y = fmaxf(v.y + bv.y, 0.f);
    v.z = fmaxf(v.z + bv.z, 0.f);
    v.w = fmaxf(v.w + bv.w, 0.f);
    *(float4*)(h + (size_t)t * 4) = v;
}

// ---------------- pooling ----------------
__global__ void k_pool_zero() {
    int t = blockIdx.x * blockDim.x + threadIdx.x;
    if (t < GMAX * HID) g_pool[t] = 0.f;
    if (t < GMAX) g_cnt[t] = 0.f;
}

__global__ void k_pool(const float* __restrict__ h,
                       const int* __restrict__ batch, int n) {
    int t = blockIdx.x * blockDim.x + threadIdx.x;
    int node = t >> 4;
    int jg   = t & 15;
    if (node >= n) return;
    int g = __ldg(batch + node);
    float4 v = *(const float4*)(h + (size_t)node * HID + jg * 4);
    atomicAdd((float4*)(g_pool + g * HID + jg * 4), v);
    if (jg == 0) atomicAdd(&g_cnt[g], 1.0f);
}

// out = pool/cnt + b2  (b2 folded into the mean: mean(x+b) = mean(x)+b)
__global__ void k_finalize(float* __restrict__ out,
                           const float* __restrict__ b2) {
    int t = blockIdx.x * blockDim.x + threadIdx.x;
    if (t >= GMAX * HID) return;
    int g = t >> 6, j = t & 63;
    out[t] = g_pool[t] / fmaxf(g_cnt[g], 1.0f) + b2[j];
}

// ---------------- launch ----------------
extern "C" void kernel_launch(void* const* d_in, const int* in_sizes, int n_in,
                              void* d_out, int out_size) {
    const float* x      = (const float*)d_in[0];
    const int*   eidx   = (const int*)d_in[1];
    const int*   batch  = (const int*)d_in[2];
    const float* W1     = (const float*)d_in[3];
    const float* b1     = (const float*)d_in[4];
    const float* W2     = (const float*)d_in[5];
    const float* b2     = (const float*)d_in[6];
    float*       out    = (float*)d_out;

    const int n = in_sizes[0] / 128;      // 100000
    const int E = in_sizes[1] / 2;        // 1600000
    const int* src = eidx;
    const int* dst = eidx + E;

    float* bufA; float* bufB;
    cudaGetSymbolAddress((void**)&bufA, g_bufA);
    cudaGetSymbolAddress((void**)&bufB, g_bufB);

    const int B = 256;
    // --- degree / dinv ---
    k_deg_init<<<(n + B - 1) / B, B>>>(n);
    k_deg_count<<<(E + B - 1) / B, B>>>(dst, E);
    k_dinv_finish<<<(n + B - 1) / B, B>>>(n);

    // --- layer 1 ---
    k_gemm_nodes<128><<<(n + 7) / 8, 256>>>(x, W1, bufA, n);          // xw1 -> A
    k_self_init<<<(n * 16 + B - 1) / B, B>>>(bufA, bufB, n);          // acc -> B
    k_scatter<<<((size_t)E * 16 + B - 1) / B, B>>>(src, dst, bufA, bufB, E);
    k_bias_relu<<<(n * 16 + B - 1) / B, B>>>(bufB, b1, bufA, n);      // h1 -> A

    // --- layer 2 ---
    k_gemm_nodes<64><<<(n + 7) / 8, 256>>>(bufA, W2, bufB, n);        // xw2 -> B
    k_self_init<<<(n * 16 + B - 1) / B, B>>>(bufB, bufA, n);          // acc -> A
    k_scatter<<<((size_t)E * 16 + B - 1) / B, B>>>(src, dst, bufB, bufA, E);

    // --- pool (b2 folded into mean) ---
    k_pool_zero<<<(GMAX * HID + B - 1) / B, B>>>();
    k_pool<<<(n * 16 + B - 1) / B, B>>>(bufA, batch, n);
    k_finalize<<<(GMAX * HID + B - 1) / B, B>>>(out, b2);
}

// round 2
// speedup vs baseline: 1.4412x; 1.4412x over previous
#include <cuda_runtime.h>
#include <cuda_bf16.h>
#include <cstdint>

#define NMAX 100000
#define GMAX 128
#define HID  64

// ---------------- scratch (no allocations allowed) ----------------
__device__ float g_dinv[NMAX];
__device__ float g_bufZ[(size_t)NMAX * HID];   // z = (xW)*dinv  (message source)
__device__ float g_bufAcc[(size_t)NMAX * HID]; // accumulator (init z, += z[src])
__device__ float g_bufH[(size_t)NMAX * HID];   // layer-1 acc kept for layer-2 input
__device__ float g_pool[GMAX * HID];
__device__ float g_cnt[GMAX];

// ---------------- degree / dinv ----------------
__global__ void k_deg_init(int n) {
    int i = blockIdx.x * blockDim.x + threadIdx.x;
    if (i < n) g_dinv[i] = 1.0f;          // self loop contributes 1
}
__global__ void k_deg_count(const int* __restrict__ dst, int E) {
    int i = blockIdx.x * blockDim.x + threadIdx.x;
    if (i < E) atomicAdd(&g_dinv[dst[i]], 1.0f);
}
__global__ void k_dinv_finish(int n) {
    int i = blockIdx.x * blockDim.x + threadIdx.x;
    if (i < n) g_dinv[i] = rsqrtf(g_dinv[i]);
}

// ---------------- batched GEMM ----------------
// Y[node,:] = f(X[node,:]) @ W, then z = Y * dinv[node] written to Z and ACC.
// f = identity (layer 1) or relu(acc1*dinv + b1) (layer 2, IN_TRANSFORM).
// One warp computes R=8 node rows; W staged in smem, x rows in registers,
// broadcast via shfl -> smem W bytes are amortized 8x vs round-1 kernel.
template <int K, bool IN_TRANSFORM>
__global__ void k_gemm(const float* __restrict__ X,
                       const float* __restrict__ Wg,
                       const float* __restrict__ bias,   // [K], only IN_TRANSFORM
                       float* __restrict__ Z,
                       float* __restrict__ ACC, int n) {
    constexpr int Q = K / 32;
    constexpr int R = 8;
    __shared__ float Ws[K * HID];
    __shared__ float bs[K];
    for (int i = threadIdx.x; i < K * HID; i += blockDim.x) Ws[i] = Wg[i];
    if (IN_TRANSFORM)
        for (int i = threadIdx.x; i < K; i += blockDim.x) bs[i] = bias[i];
    __syncthreads();

    int gw   = (blockIdx.x * blockDim.x + threadIdx.x) >> 5;
    int lane = threadIdx.x & 31;
    int base = gw * R;
    if (base >= n) return;

    float xv[R][Q];
#pragma unroll
    for (int r = 0; r < R; r++) {
        int node = base + r;
        if (node < n) {
            const float* xr = X + (size_t)node * K + lane * Q;
            float di = IN_TRANSFORM ? g_dinv[node] : 0.0f;
#pragma unroll
            for (int q = 0; q < Q; q++) {
                float v = xr[q];
                if (IN_TRANSFORM)
                    v = fmaxf(fmaf(v, di, bs[lane * Q + q]), 0.0f);
                xv[r][q] = v;
            }
        } else {
#pragma unroll
            for (int q = 0; q < Q; q++) xv[r][q] = 0.0f;
        }
    }

    float a0[R], a1[R];
#pragma unroll
    for (int r = 0; r < R; r++) { a0[r] = 0.f; a1[r] = 0.f; }

#pragma unroll
    for (int kk = 0; kk < 32; kk++) {
#pragma unroll
        for (int q = 0; q < Q; q++) {
            int k = kk * Q + q;                 // held by lane kk, slot q
            float w0 = Ws[k * HID + lane];
            float w1 = Ws[k * HID + 32 + lane];
#pragma unroll
            for (int r = 0; r < R; r++) {
                float xk = __shfl_sync(0xffffffffu, xv[r][q], kk);
                a0[r] = fmaf(xk, w0, a0[r]);
                a1[r] = fmaf(xk, w1, a1[r]);
            }
        }
    }

#pragma unroll
    for (int r = 0; r < R; r++) {
        int node = base + r;
        if (node < n) {
            float di = g_dinv[node];
            float v0 = a0[r] * di, v1 = a1[r] * di;
            size_t o = (size_t)node * HID;
            Z[o + lane] = v0;        Z[o + 32 + lane] = v1;
            ACC[o + lane] = v0;      ACC[o + 32 + lane] = v1;   // self-loop term
        }
    }
}

// ---------------- edge scatter: acc[dst] += z[src] ----------------
__global__ void k_scatter(const int* __restrict__ src,
                          const int* __restrict__ dst,
                          const float* __restrict__ z,
                          float* __restrict__ acc, int E) {
    int t = blockIdx.x * blockDim.x + threadIdx.x;
    int e  = t >> 4;          // 16 float4 lanes per edge
    int jg = t & 15;
    if (e >= E) return;
    int s = __ldg(src + e);
    int d = __ldg(dst + e);
    float4 v = *(const float4*)(z + (size_t)s * HID + jg * 4);
    atomicAdd((float4*)(acc + (size_t)d * HID + jg * 4), v);
}

// ---------------- pooling (folds final dinv scaling) ----------------
__global__ void k_pool_zero() {
    int t = blockIdx.x * blockDim.x + threadIdx.x;
    if (t < GMAX * HID) g_pool[t] = 0.f;
    if (t < GMAX) g_cnt[t] = 0.f;
}

__global__ void k_pool(const float* __restrict__ acc,
                       const int* __restrict__ batch, int n) {
    int t = blockIdx.x * blockDim.x + threadIdx.x;
    int node = t >> 4;
    int jg   = t & 15;
    if (node >= n) return;
    int g = __ldg(batch + node);
    float di = g_dinv[node];
    float4 v = *(const float4*)(acc + (size_t)node * HID + jg * 4);
    v.x *= di; v.y *= di; v.z *= di; v.w *= di;
    atomicAdd((float4*)(g_pool + g * HID + jg * 4), v);
    if (jg == 0) atomicAdd(&g_cnt[g], 1.0f);
}

// out = pool/cnt + b2 (b2 folded into the mean)
__global__ void k_finalize(float* __restrict__ out,
                           const float* __restrict__ b2) {
    int t = blockIdx.x * blockDim.x + threadIdx.x;
    if (t >= GMAX * HID) return;
    int g = t >> 6, j = t & 63;
    out[t] = g_pool[t] / fmaxf(g_cnt[g], 1.0f) + b2[j];
}

// ---------------- launch ----------------
extern "C" void kernel_launch(void* const* d_in, const int* in_sizes, int n_in,
                              void* d_out, int out_size) {
    const float* x     = (const float*)d_in[0];
    const int*   eidx  = (const int*)d_in[1];
    const int*   batch = (const int*)d_in[2];
    const float* W1    = (const float*)d_in[3];
    const float* b1    = (const float*)d_in[4];
    const float* W2    = (const float*)d_in[5];
    const float* b2    = (const float*)d_in[6];
    float*       out   = (float*)d_out;

    const int n = in_sizes[0] / 128;      // 100000
    const int E = in_sizes[1] / 2;        // 1600000
    const int* src = eidx;
    const int* dst = eidx + E;

    float *z, *acc, *h1;
    cudaGetSymbolAddress((void**)&z,   g_bufZ);
    cudaGetSymbolAddress((void**)&acc, g_bufAcc);
    cudaGetSymbolAddress((void**)&h1,  g_bufH);

    const int B = 256;
    const int gemm_blocks = (n + 63) / 64;   // 8 warps * 8 nodes per block

    // --- degree / dinv ---
    k_deg_init<<<(n + B - 1) / B, B>>>(n);
    k_deg_count<<<(E + B - 1) / B, B>>>(dst, E);
    k_dinv_finish<<<(n + B - 1) / B, B>>>(n);

    // --- layer 1: z1 = (x@W1)*dinv -> g_bufZ, acc1 init = z1 -> g_bufH ---
    k_gemm<128, false><<<gemm_blocks, 256>>>(x, W1, nullptr, z, h1, n);
    k_scatter<<<((size_t)E * 16 + B - 1) / B, B>>>(src, dst, z, h1, E);
    // h1 now holds acc1; layer-2 gemm applies relu(acc1*dinv + b1) on load.

    // --- layer 2: z2 = (relu(acc1*dinv+b1)@W2)*dinv -> z, acc2 -> acc ---
    k_gemm<64, true><<<gemm_blocks, 256>>>(h1, W2, b1, z, acc, n);
    k_scatter<<<((size_t)E * 16 + B - 1) / B, B>>>(src, dst, z, acc, E);

    // --- pool: mean over graphs of acc2*dinv, + b2 ---
    k_pool_zero<<<(GMAX * HID + B - 1) / B, B>>>();
    k_pool<<<(n * 16 + B - 1) / B, B>>>(acc, batch, n);
    k_finalize<<<(GMAX * HID + B - 1) / B, B>>>(out, b2);
}

// round 3
// speedup vs baseline: 1.7423x; 1.2090x over previous
#include <cuda_runtime.h>
#include <cuda_bf16.h>
#include <cstdint>

#define NMAX 100000
#define EMAX 1600000
#define GMAX 128
#define HID  64
#define NB_MAX 512      // max scan blocks (ceil(NMAX/256) = 391)

// ---------------- scratch (no allocations allowed) ----------------
__device__ float g_dinv[NMAX];
__device__ int   g_deg[NMAX];
__device__ int   g_off[NMAX];
__device__ int   g_cursor[NMAX];
__device__ int   g_csr_src[EMAX];
__device__ int   g_bsum[NB_MAX];
__device__ int   g_boff[NB_MAX];
__device__ float g_bufZ[(size_t)NMAX * HID];   // z = (xW)*dinv (message source)
__device__ float g_bufS[(size_t)NMAX * HID];   // S = sum of z over (A+I) nbrs
__device__ float g_pool[GMAX * HID];
__device__ float g_cnt[GMAX];

// ================= CSR construction =================
__global__ void k_zero_deg(int n) {
    int i = blockIdx.x * blockDim.x + threadIdx.x;
    if (i < n) g_deg[i] = 0;
}

__global__ void k_deg_count(const int* __restrict__ dst, int E) {
    int i = blockIdx.x * blockDim.x + threadIdx.x;
    if (i < E) atomicAdd(&g_deg[dst[i]], 1);
}

__global__ void k_block_sum(int n) {
    __shared__ int s[256];
    int i = blockIdx.x * 256 + threadIdx.x;
    int v = (i < n) ? g_deg[i] : 0;
    s[threadIdx.x] = v;
    __syncthreads();
    for (int o = 128; o > 0; o >>= 1) {
        if (threadIdx.x < o) s[threadIdx.x] += s[threadIdx.x + o];
        __syncthreads();
    }
    if (threadIdx.x == 0) g_bsum[blockIdx.x] = s[0];
}

__global__ void k_top_scan(int nb) {
    __shared__ int s[NB_MAX];
    int t = threadIdx.x;
    int v = (t < nb) ? g_bsum[t] : 0;
    s[t] = v;
    __syncthreads();
    for (int o = 1; o < NB_MAX; o <<= 1) {
        int x = (t >= o) ? s[t - o] : 0;
        __syncthreads();
        s[t] += x;
        __syncthreads();
    }
    if (t < nb) g_boff[t] = s[t] - v;   // exclusive
}

__global__ void k_scan_apply(int n) {
    __shared__ int s[256];
    int t = threadIdx.x;
    int i = blockIdx.x * 256 + t;
    int d = (i < n) ? g_deg[i] : 0;
    s[t] = d;
    __syncthreads();
    for (int o = 1; o < 256; o <<= 1) {
        int x = (t >= o) ? s[t - o] : 0;
        __syncthreads();
        s[t] += x;
        __syncthreads();
    }
    if (i < n) {
        int off = g_boff[blockIdx.x] + s[t] - d;   // exclusive scan value
        g_off[i]    = off;
        g_cursor[i] = off;
        g_dinv[i]   = rsqrtf((float)d + 1.0f);     // +1 self loop
    }
}

__global__ void k_csr_fill(const int* __restrict__ src,
                           const int* __restrict__ dst, int E) {
    int e = blockIdx.x * blockDim.x + threadIdx.x;
    if (e >= E) return;
    int d = dst[e];
    int p = atomicAdd(&g_cursor[d], 1);
    g_csr_src[p] = src[e];
}

// ================= tiled GEMM =================
// Z[node,:] = f(X[node,:]) @ W * dinv[node]
// f = identity (layer 1) or relu(S*dinv + b1) (layer 2, IN_TRANSFORM).
// Block: 256 threads, tile BM=128 nodes x BN=64 cols, full K in smem.
// Per thread: 4 rows x 8 cols register micro-tile; X-tile & W in smem.
template <int K, bool IN_TRANSFORM>
__global__ void __launch_bounds__(256)
k_gemm(const float* __restrict__ X,
       const float* __restrict__ Wg,
       const float* __restrict__ bias,
       float* __restrict__ Z, int n) {
    constexpr int BM = 128;
    constexpr int S  = K + 4;          // X-tile row stride (floats), 16B aligned
    extern __shared__ float smem[];
    float* Xs = smem;                  // [BM][S]
    float* Ws = smem + BM * S;         // [K][64]

    const int tid  = threadIdx.x;
    const int base = blockIdx.x * BM;

    // load W (coalesced)
    for (int i = tid; i < K * 16; i += 256) {       // K*64/4 float4
        ((float4*)Ws)[i] = ((const float4*)Wg)[i];
    }

    // load X tile (coalesced float4), optional input transform, zero-fill OOB
    constexpr int F4_PER_ROW = K / 4;
    for (int f = tid; f < BM * F4_PER_ROW; f += 256) {
        int m  = f / F4_PER_ROW;
        int kc = f % F4_PER_ROW;
        int node = base + m;
        float4 v = make_float4(0.f, 0.f, 0.f, 0.f);
        if (node < n) {
            v = ((const float4*)(X + (size_t)node * K))[kc];
            if (IN_TRANSFORM) {
                float di = g_dinv[node];
                int k0 = kc * 4;
                v.x = fmaxf(fmaf(v.x, di, __ldg(bias + k0 + 0)), 0.f);
                v.y = fmaxf(fmaf(v.y, di, __ldg(bias + k0 + 1)), 0.f);
                v.z = fmaxf(fmaf(v.z, di, __ldg(bias + k0 + 2)), 0.f);
                v.w = fmaxf(fmaf(v.w, di, __ldg(bias + k0 + 3)), 0.f);
            }
        }
        *(float4*)(Xs + m * S + kc * 4) = v;
    }
    __syncthreads();

    // micro-tile: rows row0..row0+3, cols col0..col0+7
    const int row0 = (tid >> 3) * 4;
    const int col0 = (tid & 7) * 8;

    float acc[4][8];
#pragma unroll
    for (int i = 0; i < 4; i++)
#pragma unroll
        for (int j = 0; j < 8; j++) acc[i][j] = 0.f;

#pragma unroll 4
    for (int k = 0; k < K; k++) {
        float a0 = Xs[(row0 + 0) * S + k];
        float a1 = Xs[(row0 + 1) * S + k];
        float a2 = Xs[(row0 + 2) * S + k];
        float a3 = Xs[(row0 + 3) * S + k];
        float4 blo = *(float4*)(Ws + k * 64 + col0);
        float4 bhi = *(float4*)(Ws + k * 64 + col0 + 4);
        float b[8] = {blo.x, blo.y, blo.z, blo.w, bhi.x, bhi.y, bhi.z, bhi.w};
#pragma unroll
        for (int j = 0; j < 8; j++) {
            acc[0][j] = fmaf(a0, b[j], acc[0][j]);
            acc[1][j] = fmaf(a1, b[j], acc[1][j]);
            acc[2][j] = fmaf(a2, b[j], acc[2][j]);
            acc[3][j] = fmaf(a3, b[j], acc[3][j]);
        }
    }

#pragma unroll
    for (int i = 0; i < 4; i++) {
        int node = base + row0 + i;
        if (node < n) {
            float di = g_dinv[node];
            float4 lo = make_float4(acc[i][0]*di, acc[i][1]*di, acc[i][2]*di, acc[i][3]*di);
            float4 hi = make_float4(acc[i][4]*di, acc[i][5]*di, acc[i][6]*di, acc[i][7]*di);
            float* zr = Z + (size_t)node * HID + col0;
            *(float4*)zr = lo;
            *(float4*)(zr + 4) = hi;
        }
    }
}

// ================= CSR gather-aggregate (no atomics on features) =======
// S[d] = z[d] + sum_{s->d} z[s];  optionally fused with mean-pool scatter.
template <bool FUSE_POOL>
__global__ void k_aggregate(const float* __restrict__ z,
                            float* __restrict__ Sout,
                            const int* __restrict__ batch, int n) {
    int t    = blockIdx.x * blockDim.x + threadIdx.x;
    int node = t >> 4;
    int jg   = t & 15;
    if (node >= n) return;

    const float4* z4 = (const float4*)z;
    float4 acc = __ldg(z4 + (size_t)node * 16 + jg);   // self term

    int o  = __ldg(g_off + node);
    int dg = __ldg(g_deg + node);
    int i = 0;
    for (; i + 2 <= dg; i += 2) {
        int s0 = __ldg(g_csr_src + o + i);
        int s1 = __ldg(g_csr_src + o + i + 1);
        float4 v0 = __ldg(z4 + (size_t)s0 * 16 + jg);
        float4 v1 = __ldg(z4 + (size_t)s1 * 16 + jg);
        acc.x += v0.x + v1.x; acc.y += v0.y + v1.y;
        acc.z += v0.z + v1.z; acc.w += v0.w + v1.w;
    }
    if (i < dg) {
        int s0 = __ldg(g_csr_src + o + i);
        float4 v0 = __ldg(z4 + (size_t)s0 * 16 + jg);
        acc.x += v0.x; acc.y += v0.y; acc.z += v0.z; acc.w += v0.w;
    }

    if (FUSE_POOL) {
        float di = g_dinv[node];
        acc.x *= di; acc.y *= di; acc.z *= di; acc.w *= di;
        int g = __ldg(batch + node);
        atomicAdd((float4*)(g_pool + g * HID + jg * 4), acc);
        if (jg == 0) atomicAdd(&g_cnt[g], 1.0f);
    } else {
        ((float4*)Sout)[(size_t)node * 16 + jg] = acc;  // raw sum; consumer scales
    }
}

// ================= pooling epilogue =================
__global__ void k_pool_zero() {
    int t = blockIdx.x * blockDim.x + threadIdx.x;
    if (t < GMAX * HID) g_pool[t] = 0.f;
    if (t < GMAX) g_cnt[t] = 0.f;
}

__global__ void k_finalize(float* __restrict__ out,
                           const float* __restrict__ b2) {
    int t = blockIdx.x * blockDim.x + threadIdx.x;
    if (t >= GMAX * HID) return;
    int g = t >> 6, j = t & 63;
    out[t] = g_pool[t] / fmaxf(g_cnt[g], 1.0f) + b2[j];
}

// ================= launch =================
extern "C" void kernel_launch(void* const* d_in, const int* in_sizes, int n_in,
                              void* d_out, int out_size) {
    const float* x     = (const float*)d_in[0];
    const int*   eidx  = (const int*)d_in[1];
    const int*   batch = (const int*)d_in[2];
    const float* W1    = (const float*)d_in[3];
    const float* b1    = (const float*)d_in[4];
    const float* W2    = (const float*)d_in[5];
    const float* b2    = (const float*)d_in[6];
    float*       out   = (float*)d_out;

    const int n = in_sizes[0] / 128;      // 100000
    const int E = in_sizes[1] / 2;        // 1600000
    const int* src = eidx;
    const int* dst = eidx + E;

    float *z, *Sbuf;
    cudaGetSymbolAddress((void**)&z,    g_bufZ);
    cudaGetSymbolAddress((void**)&Sbuf, g_bufS);

    const int B = 256;
    const int NBn = (n + 255) / 256;
    const int NBe = (E + 255) / 256;
    const int gemm_grid = (n + 127) / 128;
    const int agg_grid  = (n * 16 + B - 1) / B;

    const int smem1 = (128 * (128 + 4) + 128 * 64) * 4;   // 100352 B
    const int smem2 = (128 * (64 + 4)  +  64 * 64) * 4;   //  51200 B
    cudaFuncSetAttribute(k_gemm<128, false>,
                         cudaFuncAttributeMaxDynamicSharedMemorySize, smem1);
    cudaFuncSetAttribute(k_gemm<64, true>,
                         cudaFuncAttributeMaxDynamicSharedMemorySize, smem2);

    // --- CSR build ---
    k_zero_deg<<<NBn, B>>>(n);
    k_deg_count<<<NBe, B>>>(dst, E);
    k_block_sum<<<NBn, B>>>(n);
    k_top_scan<<<1, NB_MAX>>>(NBn);
    k_scan_apply<<<NBn, B>>>(n);
    k_csr_fill<<<NBe, B>>>(src, dst, E);

    // --- layer 1 ---
    k_gemm<128, false><<<gemm_grid, 256, smem1>>>(x, W1, nullptr, z, n);
    k_aggregate<false><<<agg_grid, B>>>(z, Sbuf, nullptr, n);

    // --- layer 2 (input transform relu(S*dinv+b1) fused into gemm load) ---
    k_gemm<64, true><<<gemm_grid, 256, smem2>>>(Sbuf, W2, b1, z, n);

    // --- aggregate 2 fused with mean pool ---
    k_pool_zero<<<(GMAX * HID + B - 1) / B, B>>>();
    k_aggregate<true><<<agg_grid, B>>>(z, nullptr, batch, n);
    k_finalize<<<(GMAX * HID + B - 1) / B, B>>>(out, b2);
}

// round 5
// speedup vs baseline: 1.7834x; 1.0236x over previous
#include <cuda_runtime.h>
#include <cuda_bf16.h>
#include <cstdint>

#define NMAX 100000
#define EMAX 1600000
#define GMAX 128
#define HID  64
#define NB_MAX 512      // max scan blocks (ceil(NMAX/256) = 391)

// ---------------- scratch (no allocations allowed) ----------------
__device__ float g_dinv[NMAX];
__device__ int   g_deg[NMAX];
__device__ int   g_off[NMAX];
__device__ int   g_cursor[NMAX];
__device__ int   g_csr_src[EMAX];
__device__ int   g_bsum[NB_MAX];
__device__ int   g_boff[NB_MAX];
__device__ float g_bufZ[(size_t)NMAX * HID];   // y/z buffer (message source)
__device__ float g_bufS[(size_t)NMAX * HID];   // aggregated sums
__device__ float g_pool[GMAX * HID];
__device__ float g_cnt[GMAX];

// ================= CSR construction =================
__global__ void k_zero_deg(int n) {
    int i = blockIdx.x * blockDim.x + threadIdx.x;
    if (i < n) g_deg[i] = 0;
}

__global__ void k_deg_count(const int* __restrict__ dst, int E) {
    int i = blockIdx.x * blockDim.x + threadIdx.x;
    if (i < E) atomicAdd(&g_deg[dst[i]], 1);
}

__global__ void k_block_sum(int n) {
    __shared__ int s[256];
    int i = blockIdx.x * 256 + threadIdx.x;
    int v = (i < n) ? g_deg[i] : 0;
    s[threadIdx.x] = v;
    __syncthreads();
    for (int o = 128; o > 0; o >>= 1) {
        if (threadIdx.x < o) s[threadIdx.x] += s[threadIdx.x + o];
        __syncthreads();
    }
    if (threadIdx.x == 0) g_bsum[blockIdx.x] = s[0];
}

__global__ void k_top_scan(int nb) {
    __shared__ int s[NB_MAX];
    int t = threadIdx.x;
    int v = (t < nb) ? g_bsum[t] : 0;
    s[t] = v;
    __syncthreads();
    for (int o = 1; o < NB_MAX; o <<= 1) {
        int x = (t >= o) ? s[t - o] : 0;
        __syncthreads();
        s[t] += x;
        __syncthreads();
    }
    if (t < nb) g_boff[t] = s[t] - v;   // exclusive
}

__global__ void k_scan_apply(int n) {
    __shared__ int s[256];
    int t = threadIdx.x;
    int i = blockIdx.x * 256 + t;
    int d = (i < n) ? g_deg[i] : 0;
    s[t] = d;
    __syncthreads();
    for (int o = 1; o < 256; o <<= 1) {
        int x = (t >= o) ? s[t - o] : 0;
        __syncthreads();
        s[t] += x;
        __syncthreads();
    }
    if (i < n) {
        int off = g_boff[blockIdx.x] + s[t] - d;   // exclusive scan value
        g_off[i]    = off;
        g_cursor[i] = off;
        g_dinv[i]   = rsqrtf((float)d + 1.0f);     // +1 self loop
    }
}

__global__ void k_csr_fill(const int* __restrict__ src,
                           const int* __restrict__ dst, int E) {
    int e = blockIdx.x * blockDim.x + threadIdx.x;
    if (e >= E) return;
    int d = dst[e];
    int p = atomicAdd(&g_cursor[d], 1);
    g_csr_src[p] = src[e];
}

// ================= tiled GEMM =================
// Z[node,:] = f(X[node,:]) @ W  (* dinv[node] if OUT_SCALE)
// f = identity, or relu(S*dinv + b1) when IN_TRANSFORM (layer 2).
// Layer 1 uses OUT_SCALE=false so it has NO dependence on g_dinv and can
// overlap with the CSR/dinv build on a side stream.
template <int K, bool IN_TRANSFORM, bool OUT_SCALE>
__global__ void __launch_bounds__(256)
k_gemm(const float* __restrict__ X,
       const float* __restrict__ Wg,
       const float* __restrict__ bias,
       float* __restrict__ Z, int n) {
    constexpr int BM = 128;
    constexpr int S  = K + 4;          // X-tile row stride (floats), 16B aligned
    extern __shared__ float smem[];
    float* Xs = smem;                  // [BM][S]
    float* Ws = smem + BM * S;         // [K][64]

    const int tid  = threadIdx.x;
    const int base = blockIdx.x * BM;

    // load W (coalesced)
    for (int i = tid; i < K * 16; i += 256) {       // K*64/4 float4
        ((float4*)Ws)[i] = ((const float4*)Wg)[i];
    }

    // load X tile (coalesced float4), optional input transform, zero-fill OOB
    constexpr int F4_PER_ROW = K / 4;
    for (int f = tid; f < BM * F4_PER_ROW; f += 256) {
        int m  = f / F4_PER_ROW;
        int kc = f % F4_PER_ROW;
        int node = base + m;
        float4 v = make_float4(0.f, 0.f, 0.f, 0.f);
        if (node < n) {
            v = ((const float4*)(X + (size_t)node * K))[kc];
            if (IN_TRANSFORM) {
                float di = g_dinv[node];
                int k0 = kc * 4;
                v.x = fmaxf(fmaf(v.x, di, __ldg(bias + k0 + 0)), 0.f);
                v.y = fmaxf(fmaf(v.y, di, __ldg(bias + k0 + 1)), 0.f);
                v.z = fmaxf(fmaf(v.z, di, __ldg(bias + k0 + 2)), 0.f);
                v.w = fmaxf(fmaf(v.w, di, __ldg(bias + k0 + 3)), 0.f);
            }
        }
        *(float4*)(Xs + m * S + kc * 4) = v;
    }
    __syncthreads();

    // micro-tile: rows row0..row0+3, cols col0..col0+7
    const int row0 = (tid >> 3) * 4;
    const int col0 = (tid & 7) * 8;

    float acc[4][8];
#pragma unroll
    for (int i = 0; i < 4; i++)
#pragma unroll
        for (int j = 0; j < 8; j++) acc[i][j] = 0.f;

#pragma unroll 4
    for (int k = 0; k < K; k++) {
        float a0 = Xs[(row0 + 0) * S + k];
        float a1 = Xs[(row0 + 1) * S + k];
        float a2 = Xs[(row0 + 2) * S + k];
        float a3 = Xs[(row0 + 3) * S + k];
        float4 blo = *(float4*)(Ws + k * 64 + col0);
        float4 bhi = *(float4*)(Ws + k * 64 + col0 + 4);
        float b[8] = {blo.x, blo.y, blo.z, blo.w, bhi.x, bhi.y, bhi.z, bhi.w};
#pragma unroll
        for (int j = 0; j < 8; j++) {
            acc[0][j] = fmaf(a0, b[j], acc[0][j]);
            acc[1][j] = fmaf(a1, b[j], acc[1][j]);
            acc[2][j] = fmaf(a2, b[j], acc[2][j]);
            acc[3][j] = fmaf(a3, b[j], acc[3][j]);
        }
    }

#pragma unroll
    for (int i = 0; i < 4; i++) {
        int node = base + row0 + i;
        if (node < n) {
            float di = OUT_SCALE ? g_dinv[node] : 1.0f;
            float4 lo = make_float4(acc[i][0]*di, acc[i][1]*di, acc[i][2]*di, acc[i][3]*di);
            float4 hi = make_float4(acc[i][4]*di, acc[i][5]*di, acc[i][6]*di, acc[i][7]*di);
            float* zr = Z + (size_t)node * HID + col0;
            *(float4*)zr = lo;
            *(float4*)(zr + 4) = hi;
        }
    }
}

// ================= CSR gather-aggregate (no atomics on features) =======
// SCALE_SRC=true : S[d] = Σ_{s->d} z[s]*dinv[s] + z[d]*dinv[d]  (z is raw xW)
// SCALE_SRC=false: S[d] = Σ_{s->d} z[s]          + z[d]         (z pre-scaled)
// FUSE_POOL folds the final dinv[d] scaling + graph mean-pool scatter.
template <bool SCALE_SRC, bool FUSE_POOL>
__global__ void k_aggregate(const float* __restrict__ z,
                            float* __restrict__ Sout,
                            const int* __restrict__ batch, int n) {
    int t    = blockIdx.x * blockDim.x + threadIdx.x;
    int node = t >> 4;
    int jg   = t & 15;
    if (node >= n) return;

    const float4* z4 = (const float4*)z;
    float4 acc = __ldg(z4 + (size_t)node * 16 + jg);   // self term
    if (SCALE_SRC) {
        float ds = __ldg(g_dinv + node);
        acc.x *= ds; acc.y *= ds; acc.z *= ds; acc.w *= ds;
    }

    const int o  = __ldg(g_off + node);
    const int dg = __ldg(g_deg + node);
    const int* ep = g_csr_src + o;

    int i = 0;
    float4 p0 = make_float4(0.f,0.f,0.f,0.f), p1 = p0;
    for (; i + 4 <= dg; i += 4) {
        int s0 = __ldg(ep + i);
        int s1 = __ldg(ep + i + 1);
        int s2 = __ldg(ep + i + 2);
        int s3 = __ldg(ep + i + 3);
        float4 v0 = __ldg(z4 + (size_t)s0 * 16 + jg);
        float4 v1 = __ldg(z4 + (size_t)s1 * 16 + jg);
        float4 v2 = __ldg(z4 + (size_t)s2 * 16 + jg);
        float4 v3 = __ldg(z4 + (size_t)s3 * 16 + jg);
        if (SCALE_SRC) {
            float d0 = __ldg(g_dinv + s0), d1 = __ldg(g_dinv + s1);
            float d2 = __ldg(g_dinv + s2), d3 = __ldg(g_dinv + s3);
            p0.x = fmaf(v0.x, d0, p0.x); p0.y = fmaf(v0.y, d0, p0.y);
            p0.z = fmaf(v0.z, d0, p0.z); p0.w = fmaf(v0.w, d0, p0.w);
            p0.x = fmaf(v1.x, d1, p0.x); p0.y = fmaf(v1.y, d1, p0.y);
            p0.z = fmaf(v1.z, d1, p0.z); p0.w = fmaf(v1.w, d1, p0.w);
            p1.x = fmaf(v2.x, d2, p1.x); p1.y = fmaf(v2.y, d2, p1.y);
            p1.z = fmaf(v2.z, d2, p1.z); p1.w = fmaf(v2.w, d2, p1.w);
            p1.x = fmaf(v3.x, d3, p1.x); p1.y = fmaf(v3.y, d3, p1.y);
            p1.z = fmaf(v3.z, d3, p1.z); p1.w = fmaf(v3.w, d3, p1.w);
        } else {
            p0.x += v0.x + v1.x; p0.y += v0.y + v1.y;
            p0.z += v0.z + v1.z; p0.w += v0.w + v1.w;
            p1.x += v2.x + v3.x; p1.y += v2.y + v3.y;
            p1.z += v2.z + v3.z; p1.w += v2.w + v3.w;
        }
    }
    for (; i < dg; i++) {
        int s0 = __ldg(ep + i);
        float4 v0 = __ldg(z4 + (size_t)s0 * 16 + jg);
        float d0 = SCALE_SRC ? __ldg(g_dinv + s0) : 1.0f;
        p0.x = fmaf(v0.x, d0, p0.x); p0.y = fmaf(v0.y, d0, p0.y);
        p0.z = fmaf(v0.z, d0, p0.z); p0.w = fmaf(v0.w, d0, p0.w);
    }
    acc.x += p0.x + p1.x; acc.y += p0.y + p1.y;
    acc.z += p0.z + p1.z; acc.w += p0.w + p1.w;

    if (FUSE_POOL) {
        float di = g_dinv[node];
        acc.x *= di; acc.y *= di; acc.z *= di; acc.w *= di;
        int g = __ldg(batch + node);
        atomicAdd((float4*)(g_pool + g * HID + jg * 4), acc);
        if (jg == 0) atomicAdd(&g_cnt[g], 1.0f);
    } else {
        ((float4*)Sout)[(size_t)node * 16 + jg] = acc;  // raw sum; consumer scales
    }
}

// ================= pooling epilogue =================
__global__ void k_pool_zero() {
    int t = blockIdx.x * blockDim.x + threadIdx.x;
    if (t < GMAX * HID) g_pool[t] = 0.f;
    if (t < GMAX) g_cnt[t] = 0.f;
}

__global__ void k_finalize(float* __restrict__ out,
                           const float* __restrict__ b2) {
    int t = blockIdx.x * blockDim.x + threadIdx.x;
    if (t >= GMAX * HID) return;
    int g = t >> 6, j = t & 63;
    out[t] = g_pool[t] / fmaxf(g_cnt[g], 1.0f) + b2[j];
}

// ================= launch =================
extern "C" void kernel_launch(void* const* d_in, const int* in_sizes, int n_in,
                              void* d_out, int out_size) {
    const float* x     = (const float*)d_in[0];
    const int*   eidx  = (const int*)d_in[1];
    const int*   batch = (const int*)d_in[2];
    const float* W1    = (const float*)d_in[3];
    const float* b1    = (const float*)d_in[4];
    const float* W2    = (const float*)d_in[5];
    const float* b2    = (const float*)d_in[6];
    float*       out   = (float*)d_out;

    const int n = in_sizes[0] / 128;      // 100000
    const int E = in_sizes[1] / 2;        // 1600000
    const int* src = eidx;
    const int* dst = eidx + E;

    float *z, *Sbuf;
    cudaGetSymbolAddress((void**)&z,    g_bufZ);
    cudaGetSymbolAddress((void**)&Sbuf, g_bufS);

    const int B = 256;
    const int NBn = (n + 255) / 256;
    const int NBe = (E + 255) / 256;
    const int gemm_grid = (n + 127) / 128;
    const int agg_grid  = (n * 16 + B - 1) / B;

    const int smem1 = (128 * (128 + 4) + 128 * 64) * 4;   // 100352 B
    const int smem2 = (128 * (64 + 4)  +  64 * 64) * 4;   //  51200 B
    cudaFuncSetAttribute(k_gemm<128, false, false>,
                         cudaFuncAttributeMaxDynamicSharedMemorySize, smem1);
    cudaFuncSetAttribute(k_gemm<64, true, true>,
                         cudaFuncAttributeMaxDynamicSharedMemorySize, smem2);

    // --- fork a side stream for the CSR/dinv build ---
    // GEMM1 (OUT_SCALE=false) touches neither g_dinv nor the CSR arrays,
    // so the two branches are truly independent.
    cudaStream_t s2;
    cudaStreamCreateWithFlags(&s2, cudaStreamNonBlocking);
    cudaEvent_t evFork, evJoin;
    cudaEventCreateWithFlags(&evFork, cudaEventDisableTiming);
    cudaEventCreateWithFlags(&evJoin, cudaEventDisableTiming);

    cudaEventRecord(evFork, 0);
    cudaStreamWaitEvent(s2, evFork, 0);

    // side stream: CSR build chain + pool zeroing
    k_zero_deg<<<NBn, B, 0, s2>>>(n);
    k_deg_count<<<NBe, B, 0, s2>>>(dst, E);
    k_block_sum<<<NBn, B, 0, s2>>>(n);
    k_top_scan<<<1, NB_MAX, 0, s2>>>(NBn);
    k_scan_apply<<<NBn, B, 0, s2>>>(n);
    k_csr_fill<<<NBe, B, 0, s2>>>(src, dst, E);
    k_pool_zero<<<(GMAX * HID + B - 1) / B, B, 0, s2>>>();

    // main stream: layer-1 GEMM (raw y1 = x@W1, no dinv)
    k_gemm<128, false, false><<<gemm_grid, 256, smem1>>>(x, W1, nullptr, z, n);

    cudaEventRecord(evJoin, s2);
    cudaStreamWaitEvent(0, evJoin, 0);

    // --- aggregate 1: S[d] = Σ y1[s]*dinv[s] + y1[d]*dinv[d] ---
    k_aggregate<true, false><<<agg_grid, B>>>(z, Sbuf, nullptr, n);

    // --- layer 2: z2 = (relu(S*dinv+b1) @ W2) * dinv ---
    k_gemm<64, true, true><<<gemm_grid, 256, smem2>>>(Sbuf, W2, b1, z, n);

    // --- aggregate 2 fused with mean pool ---
    k_aggregate<false, true><<<agg_grid, B>>>(z, nullptr, batch, n);
    k_finalize<<<(GMAX * HID + B - 1) / B, B>>>(out, b2);
}

// round 7
// speedup vs baseline: 1.7892x; 1.0032x over previous
#include <cuda_runtime.h>
#include <cuda_bf16.h>
#include <cstdint>

#define NMAX 100000
#define EMAX 1600000
#define GMAX 128
#define HID  64
#define NB_MAX 512

// ---------------- scratch (no allocations allowed) ----------------
__device__ float g_dinv[NMAX];
__device__ int   g_deg[NMAX];
__device__ int   g_off[NMAX];
__device__ int   g_cursor[NMAX];
__device__ int   g_csr_src[EMAX];
__device__ int   g_bsum[NB_MAX];
__device__ int   g_boff[NB_MAX];
__device__ float g_bufZ[(size_t)NMAX * HID];   // y1 raw, then z2
__device__ float g_bufZ2[(size_t)NMAX * HID];
__device__ float g_pool[GMAX * HID];
__device__ float g_cnt[GMAX];

// ================= CSR construction =================
__global__ void k_zero_deg(int n) {
    int i = blockIdx.x * blockDim.x + threadIdx.x;
    if (i < n) g_deg[i] = 0;
}
__global__ void k_deg_count(const int* __restrict__ dst, int E) {
    int i = blockIdx.x * blockDim.x + threadIdx.x;
    if (i < E) atomicAdd(&g_deg[dst[i]], 1);
}
__global__ void k_block_sum(int n) {
    __shared__ int s[256];
    int i = blockIdx.x * 256 + threadIdx.x;
    int v = (i < n) ? g_deg[i] : 0;
    s[threadIdx.x] = v;
    __syncthreads();
    for (int o = 128; o > 0; o >>= 1) {
        if (threadIdx.x < o) s[threadIdx.x] += s[threadIdx.x + o];
        __syncthreads();
    }
    if (threadIdx.x == 0) g_bsum[blockIdx.x] = s[0];
}
__global__ void k_top_scan(int nb) {
    __shared__ int s[NB_MAX];
    int t = threadIdx.x;
    int v = (t < nb) ? g_bsum[t] : 0;
    s[t] = v;
    __syncthreads();
    for (int o = 1; o < NB_MAX; o <<= 1) {
        int x = (t >= o) ? s[t - o] : 0;
        __syncthreads();
        s[t] += x;
        __syncthreads();
    }
    if (t < nb) g_boff[t] = s[t] - v;
}
__global__ void k_scan_apply(int n) {
    __shared__ int s[256];
    int t = threadIdx.x;
    int i = blockIdx.x * 256 + t;
    int d = (i < n) ? g_deg[i] : 0;
    s[t] = d;
    __syncthreads();
    for (int o = 1; o < 256; o <<= 1) {
        int x = (t >= o) ? s[t - o] : 0;
        __syncthreads();
        s[t] += x;
        __syncthreads();
    }
    if (i < n) {
        int off = g_boff[blockIdx.x] + s[t] - d;
        g_off[i]    = off;
        g_cursor[i] = off;
        g_dinv[i]   = rsqrtf((float)d + 1.0f);
    }
}
__global__ void k_csr_fill(const int* __restrict__ src,
                           const int* __restrict__ dst, int E) {
    int e = blockIdx.x * blockDim.x + threadIdx.x;
    if (e >= E) return;
    int d = dst[e];
    int p = atomicAdd(&g_cursor[d], 1);
    g_csr_src[p] = src[e];
}

// ================= fp32 tiled GEMM (layer 1, raw output) =================
template <int K>
__global__ void __launch_bounds__(256)
k_gemm1(const float* __restrict__ X,
        const float* __restrict__ Wg,
        float* __restrict__ Z, int n) {
    constexpr int BM = 128;
    constexpr int S  = K + 4;
    extern __shared__ float smf[];
    float* Xs = smf;
    float* Ws = smf + BM * S;

    const int tid  = threadIdx.x;
    const int base = blockIdx.x * BM;

    for (int i = tid; i < K * 16; i += 256)
        ((float4*)Ws)[i] = ((const float4*)Wg)[i];

    constexpr int F4 = K / 4;
    for (int f = tid; f < BM * F4; f += 256) {
        int m  = f / F4;
        int kc = f % F4;
        int node = base + m;
        float4 v = make_float4(0.f, 0.f, 0.f, 0.f);
        if (node < n) v = ((const float4*)(X + (size_t)node * K))[kc];
        *(float4*)(Xs + m * S + kc * 4) = v;
    }
    __syncthreads();

    const int row0 = (tid >> 3) * 4;
    const int col0 = (tid & 7) * 8;

    float acc[4][8];
#pragma unroll
    for (int i = 0; i < 4; i++)
#pragma unroll
        for (int j = 0; j < 8; j++) acc[i][j] = 0.f;

#pragma unroll 4
    for (int k = 0; k < K; k++) {
        float a0 = Xs[(row0 + 0) * S + k];
        float a1 = Xs[(row0 + 1) * S + k];
        float a2 = Xs[(row0 + 2) * S + k];
        float a3 = Xs[(row0 + 3) * S + k];
        float4 blo = *(float4*)(Ws + k * 64 + col0);
        float4 bhi = *(float4*)(Ws + k * 64 + col0 + 4);
        float b[8] = {blo.x, blo.y, blo.z, blo.w, bhi.x, bhi.y, bhi.z, bhi.w};
#pragma unroll
        for (int j = 0; j < 8; j++) {
            acc[0][j] = fmaf(a0, b[j], acc[0][j]);
            acc[1][j] = fmaf(a1, b[j], acc[1][j]);
            acc[2][j] = fmaf(a2, b[j], acc[2][j]);
            acc[3][j] = fmaf(a3, b[j], acc[3][j]);
        }
    }

#pragma unroll
    for (int i = 0; i < 4; i++) {
        int node = base + row0 + i;
        if (node < n) {
            float* zr = Z + (size_t)node * HID + col0;
            *(float4*)zr = make_float4(acc[i][0], acc[i][1], acc[i][2], acc[i][3]);
            *(float4*)(zr + 4) = make_float4(acc[i][4], acc[i][5], acc[i][6], acc[i][7]);
        }
    }
}

// ========== FUSED: aggregate-1 + input-transform + GEMM2 ==========
// Per block of 128 nodes:
//   Phase A: x2[m][:] = relu( dinv[m]*( Σ_{s->m} y1[s]*dinv[s] + y1[m]*dinv[m] ) + b1 )
//            written straight into the GEMM X-tile in smem.
//   Phase B: z2[m][:] = (x2 @ W2) * dinv[m]
__global__ void __launch_bounds__(256)
k_agg_gemm2(const float* __restrict__ y1,
            const float* __restrict__ W2,     // [64][64]
            const float* __restrict__ b1,     // [64]
            float* __restrict__ Z2, int n) {
    constexpr int BM = 128;
    constexpr int K  = 64;
    constexpr int S  = K + 4;
    extern __shared__ float smf[];
    float* Xs = smf;                 // [128][68]
    float* Ws = smf + BM * S;        // [64][64]
    float* bs = Ws + K * 64;         // [64]

    const int tid  = threadIdx.x;
    const int base = blockIdx.x * BM;

    for (int i = tid; i < K * 16; i += 256)
        ((float4*)Ws)[i] = ((const float4*)W2)[i];
    if (tid < 64) bs[tid] = b1[tid];

    // ---- phase A: gather-aggregate into Xs ----
    const float4* z4 = (const float4*)y1;
#pragma unroll
    for (int p = 0; p < 8; p++) {
        int t  = tid + p * 256;          // 0..2047
        int m  = t >> 4;
        int jg = t & 15;
        int node = base + m;
        float4 acc = make_float4(0.f, 0.f, 0.f, 0.f);
        if (node < n) {
            float dn = __ldg(g_dinv + node);
            acc = __ldg(z4 + (size_t)node * 16 + jg);
            acc.x *= dn; acc.y *= dn; acc.z *= dn; acc.w *= dn;

            const int o  = __ldg(g_off + node);
            const int dg = __ldg(g_deg + node);
            const int* ep = g_csr_src + o;
            int i = 0;
            float4 p0 = make_float4(0.f,0.f,0.f,0.f), p1 = p0;
            for (; i + 4 <= dg; i += 4) {
                int s0 = __ldg(ep + i);
                int s1 = __ldg(ep + i + 1);
                int s2 = __ldg(ep + i + 2);
                int s3 = __ldg(ep + i + 3);
                float4 v0 = __ldg(z4 + (size_t)s0 * 16 + jg);
                float4 v1 = __ldg(z4 + (size_t)s1 * 16 + jg);
                float4 v2 = __ldg(z4 + (size_t)s2 * 16 + jg);
                float4 v3 = __ldg(z4 + (size_t)s3 * 16 + jg);
                float d0 = __ldg(g_dinv + s0), d1 = __ldg(g_dinv + s1);
                float d2 = __ldg(g_dinv + s2), d3 = __ldg(g_dinv + s3);
                p0.x = fmaf(v0.x, d0, p0.x); p0.y = fmaf(v0.y, d0, p0.y);
                p0.z = fmaf(v0.z, d0, p0.z); p0.w = fmaf(v0.w, d0, p0.w);
                p0.x = fmaf(v1.x, d1, p0.x); p0.y = fmaf(v1.y, d1, p0.y);
                p0.z = fmaf(v1.z, d1, p0.z); p0.w = fmaf(v1.w, d1, p0.w);
                p1.x = fmaf(v2.x, d2, p1.x); p1.y = fmaf(v2.y, d2, p1.y);
                p1.z = fmaf(v2.z, d2, p1.z); p1.w = fmaf(v2.w, d2, p1.w);
                p1.x = fmaf(v3.x, d3, p1.x); p1.y = fmaf(v3.y, d3, p1.y);
                p1.z = fmaf(v3.z, d3, p1.z); p1.w = fmaf(v3.w, d3, p1.w);
            }
            for (; i < dg; i++) {
                int s0 = __ldg(ep + i);
                float4 v0 = __ldg(z4 + (size_t)s0 * 16 + jg);
                float d0 = __ldg(g_dinv + s0);
                p0.x = fmaf(v0.x, d0, p0.x); p0.y = fmaf(v0.y, d0, p0.y);
                p0.z = fmaf(v0.z, d0, p0.z); p0.w = fmaf(v0.w, d0, p0.w);
            }
            acc.x += p0.x + p1.x; acc.y += p0.y + p1.y;
            acc.z += p0.z + p1.z; acc.w += p0.w + p1.w;

            // input transform: relu(S*dinv + b1)
            int k0 = jg * 4;
            acc.x = fmaxf(fmaf(acc.x, dn, bs[k0 + 0]), 0.f);
            acc.y = fmaxf(fmaf(acc.y, dn, bs[k0 + 1]), 0.f);
            acc.z = fmaxf(fmaf(acc.z, dn, bs[k0 + 2]), 0.f);
            acc.w = fmaxf(fmaf(acc.w, dn, bs[k0 + 3]), 0.f);
        }
        *(float4*)(Xs + m * S + jg * 4) = acc;
    }
    __syncthreads();

    // ---- phase B: tile GEMM, epilogue * dinv ----
    const int row0 = (tid >> 3) * 4;
    const int col0 = (tid & 7) * 8;

    float acc[4][8];
#pragma unroll
    for (int i = 0; i < 4; i++)
#pragma unroll
        for (int j = 0; j < 8; j++) acc[i][j] = 0.f;

#pragma unroll 4
    for (int k = 0; k < K; k++) {
        float a0 = Xs[(row0 + 0) * S + k];
        float a1 = Xs[(row0 + 1) * S + k];
        float a2 = Xs[(row0 + 2) * S + k];
        float a3 = Xs[(row0 + 3) * S + k];
        float4 blo = *(float4*)(Ws + k * 64 + col0);
        float4 bhi = *(float4*)(Ws + k * 64 + col0 + 4);
        float b[8] = {blo.x, blo.y, blo.z, blo.w, bhi.x, bhi.y, bhi.z, bhi.w};
#pragma unroll
        for (int j = 0; j < 8; j++) {
            acc[0][j] = fmaf(a0, b[j], acc[0][j]);
            acc[1][j] = fmaf(a1, b[j], acc[1][j]);
            acc[2][j] = fmaf(a2, b[j], acc[2][j]);
            acc[3][j] = fmaf(a3, b[j], acc[3][j]);
        }
    }

#pragma unroll
    for (int i = 0; i < 4; i++) {
        int node = base + row0 + i;
        if (node < n) {
            float di = g_dinv[node];
            float* zr = Z2 + (size_t)node * HID + col0;
            *(float4*)zr = make_float4(acc[i][0]*di, acc[i][1]*di,
                                       acc[i][2]*di, acc[i][3]*di);
            *(float4*)(zr + 4) = make_float4(acc[i][4]*di, acc[i][5]*di,
                                             acc[i][6]*di, acc[i][7]*di);
        }
    }
}

// ================= aggregate-2 fused with mean pool =================
__global__ void k_agg_pool(const float* __restrict__ z,
                           const int* __restrict__ batch, int n) {
    int t    = blockIdx.x * blockDim.x + threadIdx.x;
    int node = t >> 4;
    int jg   = t & 15;
    if (node >= n) return;

    const float4* z4 = (const float4*)z;
    float4 acc = __ldg(z4 + (size_t)node * 16 + jg);

    const int o  = __ldg(g_off + node);
    const int dg = __ldg(g_deg + node);
    const int* ep = g_csr_src + o;

    int i = 0;
    float4 p0 = make_float4(0.f,0.f,0.f,0.f), p1 = p0;
    for (; i + 4 <= dg; i += 4) {
        int s0 = __ldg(ep + i);
        int s1 = __ldg(ep + i + 1);
        int s2 = __ldg(ep + i + 2);
        int s3 = __ldg(ep + i + 3);
        float4 v0 = __ldg(z4 + (size_t)s0 * 16 + jg);
        float4 v1 = __ldg(z4 + (size_t)s1 * 16 + jg);
        float4 v2 = __ldg(z4 + (size_t)s2 * 16 + jg);
        float4 v3 = __ldg(z4 + (size_t)s3 * 16 + jg);
        p0.x += v0.x + v1.x; p0.y += v0.y + v1.y;
        p0.z += v0.z + v1.z; p0.w += v0.w + v1.w;
        p1.x += v2.x + v3.x; p1.y += v2.y + v3.y;
        p1.z += v2.z + v3.z; p1.w += v2.w + v3.w;
    }
    for (; i < dg; i++) {
        int s0 = __ldg(ep + i);
        float4 v0 = __ldg(z4 + (size_t)s0 * 16 + jg);
        p0.x += v0.x; p0.y += v0.y; p0.z += v0.z; p0.w += v0.w;
    }
    acc.x += p0.x + p1.x; acc.y += p0.y + p1.y;
    acc.z += p0.z + p1.z; acc.w += p0.w + p1.w;

    float di = g_dinv[node];
    acc.x *= di; acc.y *= di; acc.z *= di; acc.w *= di;
    int g = __ldg(batch + node);
    atomicAdd((float4*)(g_pool + g * HID + jg * 4), acc);
    if (jg == 0) atomicAdd(&g_cnt[g], 1.0f);
}

// ================= pooling epilogue =================
__global__ void k_pool_zero() {
    int t = blockIdx.x * blockDim.x + threadIdx.x;
    if (t < GMAX * HID) g_pool[t] = 0.f;
    if (t < GMAX) g_cnt[t] = 0.f;
}
__global__ void k_finalize(float* __restrict__ out,
                           const float* __restrict__ b2) {
    int t = blockIdx.x * blockDim.x + threadIdx.x;
    if (t >= GMAX * HID) return;
    int g = t >> 6, j = t & 63;
    out[t] = g_pool[t] / fmaxf(g_cnt[g], 1.0f) + b2[j];
}

// ================= launch =================
extern "C" void kernel_launch(void* const* d_in, const int* in_sizes, int n_in,
                              void* d_out, int out_size) {
    const float* x     = (const float*)d_in[0];
    const int*   eidx  = (const int*)d_in[1];
    const int*   batch = (const int*)d_in[2];
    const float* W1    = (const float*)d_in[3];
    const float* b1    = (const float*)d_in[4];
    const float* W2    = (const float*)d_in[5];
    const float* b2    = (const float*)d_in[6];
    float*       out   = (float*)d_out;

    const int n = in_sizes[0] / 128;
    const int E = in_sizes[1] / 2;
    const int* src = eidx;
    const int* dst = eidx + E;

    float *z, *z2;
    cudaGetSymbolAddress((void**)&z,  g_bufZ);
    cudaGetSymbolAddress((void**)&z2, g_bufZ2);

    const int B = 256;
    const int NBn = (n + 255) / 256;
    const int NBe = (E + 255) / 256;
    const int gemm_grid = (n + 127) / 128;
    const int agg_grid  = (n * 16 + B - 1) / B;

    const int smem1 = (128 * (128 + 4) + 128 * 64) * 4;        // 100352 B
    const int smemF = (128 * (64 + 4) + 64 * 64 + 64) * 4;     // 51456 B
    cudaFuncSetAttribute(k_gemm1<128>,
                         cudaFuncAttributeMaxDynamicSharedMemorySize, smem1);
    cudaFuncSetAttribute(k_agg_gemm2,
                         cudaFuncAttributeMaxDynamicSharedMemorySize, smemF);

    cudaStream_t s2;
    cudaStreamCreateWithFlags(&s2, cudaStreamNonBlocking);
    cudaEvent_t evFork, evJoin;
    cudaEventCreateWithFlags(&evFork, cudaEventDisableTiming);
    cudaEventCreateWithFlags(&evJoin, cudaEventDisableTiming);

    cudaEventRecord(evFork, 0);
    cudaStreamWaitEvent(s2, evFork, 0);

    // side stream: CSR/dinv build + pool zeroing
    k_zero_deg<<<NBn, B, 0, s2>>>(n);
    k_deg_count<<<NBe, B, 0, s2>>>(dst, E);
    k_block_sum<<<NBn, B, 0, s2>>>(n);
    k_top_scan<<<1, NB_MAX, 0, s2>>>(NBn);
    k_scan_apply<<<NBn, B, 0, s2>>>(n);
    k_csr_fill<<<NBe, B, 0, s2>>>(src, dst, E);
    k_pool_zero<<<(GMAX * HID + B - 1) / B, B, 0, s2>>>();

    // main stream: layer-1 GEMM (raw y1 = x@W1, no dinv dependence)
    k_gemm1<128><<<gemm_grid, 256, smem1>>>(x, W1, z, n);

    cudaEventRecord(evJoin, s2);
    cudaStreamWaitEvent(0, evJoin, 0);

    // fused aggregate-1 + transform + GEMM2 -> z2
    k_agg_gemm2<<<gemm_grid, 256, smemF>>>(z, W2, b1, z2, n);

    // aggregate-2 fused with mean pool
    k_agg_pool<<<agg_grid, B>>>(z2, batch, n);
    k_finalize<<<(GMAX * HID + B - 1) / B, B>>>(out, b2);
}